// round 1
// baseline (speedup 1.0000x reference)
#include <cuda_runtime.h>

#define N_NODESC 50000
#define N_EDGESC 400000
#define HID 200
#define NG 64
#define NOUT 16
#define NL 5

// ---------------- scratch (static __device__, no allocation) ----------------
static __device__ float g_x[N_NODESC * HID];   // current node features
static __device__ float g_h[N_NODESC * HID];   // x + aggregated messages
static __device__ float g_t[N_NODESC * HID];   // intermediate after GEMM1
static __device__ float g_etab[60 * HID];      // etype(3) x epos(20) edge embedding table
static __device__ float g_alpha[NL * HID];     // folded BN scale
static __device__ float g_beta[NL * HID];      // folded BN shift (incl. b1)
static __device__ int   g_deg[N_NODESC];
static __device__ int   g_off[N_NODESC + 1];
static __device__ int   g_cur[N_NODESC];
static __device__ int   g_packed[N_EDGESC];    // src | (eidx<<16)
static __device__ float g_pooled[(NL + 1) * NG * HID];
static __device__ int   g_counts[NG];

// ---------------- small setup kernels ----------------
__global__ void zero_scratch() {
    int i = blockIdx.x * blockDim.x + threadIdx.x;
    if (i < N_NODESC) { g_deg[i] = 0; g_cur[i] = 0; }
    if (i < NG) g_counts[i] = 0;
    int stride = gridDim.x * blockDim.x;
    for (int j = i; j < (NL + 1) * NG * HID; j += stride) g_pooled[j] = 0.f;
}

__global__ void node_emb_kernel(const int* __restrict__ kind, const int* __restrict__ content,
                                const float* __restrict__ kemb, const float* __restrict__ i2v,
                                const float* __restrict__ temb) {
    int n = blockIdx.x;
    int t = threadIdx.x;
    if (t >= HID) return;
    int k = kind[n];
    float v = kemb[k * HID + t];
    v += (k == 0) ? i2v[content[n] * HID + t] : temb[t];
    g_x[n * HID + t] = v;
}

__global__ void etab_kernel(const float* __restrict__ etype_emb, const float* __restrict__ epos_emb) {
    int idx = blockIdx.x * blockDim.x + threadIdx.x;
    if (idx >= 60 * HID) return;
    int e = idx / HID, t = idx % HID;
    g_etab[idx] = etype_emb[(e / 20) * HID + t] + epos_emb[(e % 20) * HID + t];
}

__global__ void bnfold_kernel(const float* __restrict__ bn_g, const float* __restrict__ bn_b,
                              const float* __restrict__ bn_m, const float* __restrict__ bn_v,
                              const float* __restrict__ b1) {
    int idx = blockIdx.x * blockDim.x + threadIdx.x;
    if (idx >= NL * HID) return;
    float a = bn_g[idx] * rsqrtf(bn_v[idx] + 1e-5f);
    g_alpha[idx] = a;
    g_beta[idx] = (b1[idx] - bn_m[idx]) * a + bn_b[idx];
}

// ---------------- CSR build (counting sort by dst) ----------------
__global__ void hist_kernel(const int* __restrict__ dst) {
    int j = blockIdx.x * blockDim.x + threadIdx.x;
    if (j < N_EDGESC) atomicAdd(&g_deg[dst[j]], 1);
}

__global__ void scan_kernel() {
    __shared__ int s[1024];
    __shared__ int carry;
    int lt = threadIdx.x;
    if (lt == 0) carry = 0;
    __syncthreads();
    for (int base = 0; base < N_NODESC; base += 1024) {
        int i = base + lt;
        int v = (i < N_NODESC) ? g_deg[i] : 0;
        s[lt] = v;
        __syncthreads();
        for (int ofs = 1; ofs < 1024; ofs <<= 1) {
            int tv = (lt >= ofs) ? s[lt - ofs] : 0;
            __syncthreads();
            s[lt] += tv;
            __syncthreads();
        }
        if (i < N_NODESC) g_off[i + 1] = carry + s[lt];
        int total = s[1023];
        __syncthreads();
        if (lt == 0) carry += total;
        __syncthreads();
    }
    if (threadIdx.x == 0) g_off[0] = 0;
}

__global__ void scatter_kernel(const int* __restrict__ src, const int* __restrict__ dst,
                               const int* __restrict__ etype, const int* __restrict__ epos) {
    int j = blockIdx.x * blockDim.x + threadIdx.x;
    if (j >= N_EDGESC) return;
    int d = dst[j];
    int pos = g_off[d] + atomicAdd(&g_cur[d], 1);
    int ep = epos[j]; if (ep > 19) ep = 19;
    int ei = etype[j] * 20 + ep;
    g_packed[pos] = src[j] | (ei << 16);
}

__global__ void counts_kernel(const int* __restrict__ batch) {
    int i = blockIdx.x * blockDim.x + threadIdx.x;
    if (i < N_NODESC) atomicAdd(&g_counts[batch[i]], 1);
}

// ---------------- per-layer kernels ----------------
// h[n] = x[n] + sum_{edges into n} relu(x[src] + etab[eidx])
__global__ void aggregate_kernel() {
    int n = blockIdx.x;
    int t = threadIdx.x;
    if (t >= HID) return;
    float acc = g_x[n * HID + t];
    int s0 = g_off[n], s1 = g_off[n + 1];
    for (int k = s0; k < s1; k++) {
        int p = g_packed[k];
        int s = p & 0xFFFF;
        int ei = p >> 16;
        float v = g_x[s * HID + t] + g_etab[ei * HID + t];
        acc += fmaxf(v, 0.f);
    }
    g_h[n * HID + t] = acc;
}

// C[M,200] = relu(epilogue(A[M,200] @ B[200,200]))
// MODE 0: A=g_h, C=g_t, epilogue = v*alpha[col]+beta[col]   (Linear1 + folded BN)
// MODE 1: A=g_t, C=g_x, epilogue = v + bias[col]            (Linear2 + bias)
// Tiling: BM=128, BN=40 (5 tiles cover N=200 exactly), BK=16, 256 threads, 4x5 microtile.
template <int MODE>
__global__ void __launch_bounds__(256) gemm_kernel(const float* __restrict__ B,
                                                   const float* __restrict__ bias,
                                                   int layer) {
    const float* __restrict__ A = (MODE == 0) ? g_h : g_t;
    float* __restrict__ C = (MODE == 0) ? g_t : g_x;

    __shared__ __align__(16) float As[16][132];  // [k][row], padded vs bank conflicts
    __shared__ float Bs[16][40];

    int tid = threadIdx.x;
    int tx = tid & 7;    // 8 col groups * 5 cols
    int ty = tid >> 3;   // 32 row groups * 4 rows
    int row0 = blockIdx.x * 128;
    int col0 = blockIdx.y * 40;

    float acc[4][5];
#pragma unroll
    for (int i = 0; i < 4; i++)
#pragma unroll
        for (int j = 0; j < 5; j++) acc[i][j] = 0.f;

    int lr = tid >> 1;          // 128 rows, 2 threads per row
    int lk = (tid & 1) * 8;     // each thread: 2 float4 (k offsets lk, lk+4)
    bool rok = (row0 + lr) < N_NODESC;
    const float* aBase = A + (size_t)(row0 + lr) * HID;

    for (int k0 = 0; k0 < HID; k0 += 16) {
        float4 v0 = make_float4(0.f, 0.f, 0.f, 0.f), v1 = v0;
        if (rok) {
            if (k0 + lk < HID)     v0 = *(const float4*)(aBase + k0 + lk);
            if (k0 + lk + 4 < HID) v1 = *(const float4*)(aBase + k0 + lk + 4);
        }
        As[lk + 0][lr] = v0.x; As[lk + 1][lr] = v0.y; As[lk + 2][lr] = v0.z; As[lk + 3][lr] = v0.w;
        As[lk + 4][lr] = v1.x; As[lk + 5][lr] = v1.y; As[lk + 6][lr] = v1.z; As[lk + 7][lr] = v1.w;

        for (int idx = tid; idx < 16 * 40; idx += 256) {
            int kk = idx / 40, c = idx % 40;
            int gk = k0 + kk;
            Bs[kk][c] = (gk < HID) ? B[gk * HID + col0 + c] : 0.f;
        }
        __syncthreads();

#pragma unroll
        for (int kk = 0; kk < 16; kk++) {
            float4 av = *(const float4*)&As[kk][ty * 4];
            float a0 = av.x, a1 = av.y, a2 = av.z, a3 = av.w;
            float b[5];
#pragma unroll
            for (int j = 0; j < 5; j++) b[j] = Bs[kk][tx * 5 + j];
#pragma unroll
            for (int j = 0; j < 5; j++) {
                acc[0][j] += a0 * b[j];
                acc[1][j] += a1 * b[j];
                acc[2][j] += a2 * b[j];
                acc[3][j] += a3 * b[j];
            }
        }
        __syncthreads();
    }

#pragma unroll
    for (int i = 0; i < 4; i++) {
        int row = row0 + ty * 4 + i;
        if (row < N_NODESC) {
#pragma unroll
            for (int j = 0; j < 5; j++) {
                int col = col0 + tx * 5 + j;
                float v = acc[i][j];
                if (MODE == 0)
                    v = v * g_alpha[layer * HID + col] + g_beta[layer * HID + col];
                else
                    v = v + bias[col];
                C[(size_t)row * HID + col] = fmaxf(v, 0.f);
            }
        }
    }
}

// run-accumulated segment-sum pooling over sorted batch_vec
__global__ void pool_kernel(const int* __restrict__ batch, int layer) {
    int t = threadIdx.x;
    if (t >= HID) return;
    int i0 = blockIdx.x * 64;
    int i1 = i0 + 64; if (i1 > N_NODESC) i1 = N_NODESC;
    if (i0 >= N_NODESC) return;
    float* pooled = g_pooled + layer * NG * HID;
    float acc = 0.f;
    int cur = batch[i0];
    for (int i = i0; i < i1; i++) {
        int g = batch[i];
        if (g != cur) { atomicAdd(&pooled[cur * HID + t], acc); acc = 0.f; cur = g; }
        acc += g_x[i * HID + t];
    }
    atomicAdd(&pooled[cur * HID + t], acc);
}

__global__ void final_kernel(const float* __restrict__ fcW, const float* __restrict__ fcb,
                             float* __restrict__ out) {
    __shared__ float red[256];
    int g = blockIdx.x;
    int t = threadIdx.x;
    int o = t & 15, seg = t >> 4;
    float acc = 0.f;
    for (int i = 0; i < NL + 1; i++) {
        const float* p = g_pooled + (i * NG + g) * HID;
        const float* w = fcW + i * HID * NOUT;
        for (int tt = seg; tt < HID; tt += 16)
            acc += p[tt] * w[tt * NOUT + o];
    }
    red[t] = acc;
    __syncthreads();
    for (int s = 8; s >= 1; s >>= 1) {
        if (seg < s) red[t] += red[t + s * 16];
        __syncthreads();
    }
    if (seg == 0) {
        float bias = 0.f;
        for (int i = 0; i < NL + 1; i++) bias += fcb[i * NOUT + o];
        float cnt = fmaxf((float)g_counts[g], 1.f);
        out[g * NOUT + o] = red[o] / cnt + bias;
    }
}

// ---------------- launch ----------------
extern "C" void kernel_launch(void* const* d_in, const int* in_sizes, int n_in,
                              void* d_out, int out_size) {
    (void)in_sizes; (void)n_in; (void)out_size;
    const int* node_kind    = (const int*)d_in[0];
    const int* node_content = (const int*)d_in[1];
    const int* edge_index   = (const int*)d_in[2];
    const int* edge_type    = (const int*)d_in[3];
    const int* edge_pos     = (const int*)d_in[4];
    const int* batch_vec    = (const int*)d_in[5];
    const float* kind_emb   = (const float*)d_in[6];
    const float* inst2vec   = (const float*)d_in[7];
    const float* type_emb   = (const float*)d_in[8];
    const float* etype_emb  = (const float*)d_in[9];
    const float* epos_emb   = (const float*)d_in[10];
    const float* W1         = (const float*)d_in[11];
    const float* b1         = (const float*)d_in[12];
    const float* bn_g       = (const float*)d_in[13];
    const float* bn_b       = (const float*)d_in[14];
    const float* bn_m       = (const float*)d_in[15];
    const float* bn_v       = (const float*)d_in[16];
    const float* W2         = (const float*)d_in[17];
    const float* b2         = (const float*)d_in[18];
    const float* fc_W       = (const float*)d_in[19];
    const float* fc_b       = (const float*)d_in[20];
    float* out = (float*)d_out;

    const int* src = edge_index;
    const int* dst = edge_index + N_EDGESC;

    zero_scratch<<<(N_NODESC + 255) / 256, 256>>>();
    node_emb_kernel<<<N_NODESC, 256>>>(node_kind, node_content, kind_emb, inst2vec, type_emb);
    etab_kernel<<<(60 * HID + 255) / 256, 256>>>(etype_emb, epos_emb);
    bnfold_kernel<<<(NL * HID + 255) / 256, 256>>>(bn_g, bn_b, bn_m, bn_v, b1);

    hist_kernel<<<(N_EDGESC + 255) / 256, 256>>>(dst);
    scan_kernel<<<1, 1024>>>();
    scatter_kernel<<<(N_EDGESC + 255) / 256, 256>>>(src, dst, edge_type, edge_pos);
    counts_kernel<<<(N_NODESC + 255) / 256, 256>>>(batch_vec);

    dim3 ggrid((N_NODESC + 127) / 128, 5);
    pool_kernel<<<(N_NODESC + 63) / 64, 256>>>(batch_vec, 0);
    for (int l = 0; l < NL; l++) {
        aggregate_kernel<<<N_NODESC, 256>>>();
        gemm_kernel<0><<<ggrid, 256>>>(W1 + l * HID * HID, nullptr, l);
        gemm_kernel<1><<<ggrid, 256>>>(W2 + l * HID * HID, b2 + l * HID, l);
        pool_kernel<<<(N_NODESC + 63) / 64, 256>>>(batch_vec, l + 1);
    }
    final_kernel<<<NG, 256>>>(fc_W, fc_b, out);
}

// round 4
// speedup vs baseline: 1.2570x; 1.2570x over previous
#include <cuda_runtime.h>
#include <cstdint>

#define N_NODESC 50000
#define N_EDGESC 400000
#define HID 200
#define NG 64
#define NOUT 16
#define NL 5

// ---------------- scratch (static __device__, no allocation) ----------------
static __device__ float g_x[N_NODESC * HID];   // current node features
static __device__ float g_h[N_NODESC * HID];   // x + aggregated messages
static __device__ float g_t[N_NODESC * HID];   // intermediate after GEMM1
static __device__ float g_etab[60 * HID];      // etype(3) x epos(20) edge embedding table
static __device__ float g_alpha[NL * HID];     // folded BN scale
static __device__ float g_beta[NL * HID];      // folded BN shift (incl. b1)
static __device__ int   g_deg[N_NODESC];
static __device__ int   g_off[N_NODESC + 1];
static __device__ int   g_cur[N_NODESC];
static __device__ int   g_packed[N_EDGESC];    // src | (eidx<<16)
static __device__ float g_pooled[(NL + 1) * NG * HID];
static __device__ int   g_counts[NG];

// ---------------- small setup kernels ----------------
__global__ void zero_scratch() {
    int i = blockIdx.x * blockDim.x + threadIdx.x;
    if (i < N_NODESC) { g_deg[i] = 0; g_cur[i] = 0; }
    if (i < NG) g_counts[i] = 0;
    int stride = gridDim.x * blockDim.x;
    for (int j = i; j < (NL + 1) * NG * HID; j += stride) g_pooled[j] = 0.f;
}

__global__ void node_emb_kernel(const int* __restrict__ kind, const int* __restrict__ content,
                                const float* __restrict__ kemb, const float* __restrict__ i2v,
                                const float* __restrict__ temb) {
    int n = blockIdx.x;
    int t = threadIdx.x;
    if (t >= HID) return;
    int k = kind[n];
    float v = kemb[k * HID + t];
    v += (k == 0) ? i2v[content[n] * HID + t] : temb[t];
    g_x[n * HID + t] = v;
}

__global__ void etab_kernel(const float* __restrict__ etype_emb, const float* __restrict__ epos_emb) {
    int idx = blockIdx.x * blockDim.x + threadIdx.x;
    if (idx >= 60 * HID) return;
    int e = idx / HID, t = idx % HID;
    g_etab[idx] = etype_emb[(e / 20) * HID + t] + epos_emb[(e % 20) * HID + t];
}

__global__ void bnfold_kernel(const float* __restrict__ bn_g, const float* __restrict__ bn_b,
                              const float* __restrict__ bn_m, const float* __restrict__ bn_v,
                              const float* __restrict__ b1) {
    int idx = blockIdx.x * blockDim.x + threadIdx.x;
    if (idx >= NL * HID) return;
    float a = bn_g[idx] * rsqrtf(bn_v[idx] + 1e-5f);
    g_alpha[idx] = a;
    g_beta[idx] = (b1[idx] - bn_m[idx]) * a + bn_b[idx];
}

// ---------------- CSR build (counting sort by dst) ----------------
__global__ void hist_kernel(const int* __restrict__ dst) {
    int j = blockIdx.x * blockDim.x + threadIdx.x;
    if (j < N_EDGESC) atomicAdd(&g_deg[dst[j]], 1);
}

__global__ void scan_kernel() {
    __shared__ int s[1024];
    __shared__ int carry;
    int lt = threadIdx.x;
    if (lt == 0) carry = 0;
    __syncthreads();
    for (int base = 0; base < N_NODESC; base += 1024) {
        int i = base + lt;
        int v = (i < N_NODESC) ? g_deg[i] : 0;
        s[lt] = v;
        __syncthreads();
        for (int ofs = 1; ofs < 1024; ofs <<= 1) {
            int tv = (lt >= ofs) ? s[lt - ofs] : 0;
            __syncthreads();
            s[lt] += tv;
            __syncthreads();
        }
        if (i < N_NODESC) g_off[i + 1] = carry + s[lt];
        int total = s[1023];
        __syncthreads();
        if (lt == 0) carry += total;
        __syncthreads();
    }
    if (threadIdx.x == 0) g_off[0] = 0;
}

__global__ void scatter_kernel(const int* __restrict__ src, const int* __restrict__ dst,
                               const int* __restrict__ etype, const int* __restrict__ epos) {
    int j = blockIdx.x * blockDim.x + threadIdx.x;
    if (j >= N_EDGESC) return;
    int d = dst[j];
    int pos = g_off[d] + atomicAdd(&g_cur[d], 1);
    int ep = epos[j]; if (ep > 19) ep = 19;
    int ei = etype[j] * 20 + ep;
    g_packed[pos] = src[j] | (ei << 16);
}

__global__ void counts_kernel(const int* __restrict__ batch) {
    int i = blockIdx.x * blockDim.x + threadIdx.x;
    if (i < N_NODESC) atomicAdd(&g_counts[batch[i]], 1);
}

// ---------------- per-layer kernels ----------------
// h[n] = x[n] + sum_{edges into n} relu(x[src] + etab[eidx])
// 2-way unrolled over edges to double gather MLP.
__global__ void aggregate_kernel() {
    int n = blockIdx.x;
    int t = threadIdx.x;
    if (t >= HID) return;
    float acc = g_x[n * HID + t];
    int s0 = g_off[n], s1 = g_off[n + 1];
    int k = s0;
    for (; k + 1 < s1; k += 2) {
        int p0 = g_packed[k], p1 = g_packed[k + 1];
        float va = g_x[(p0 & 0xFFFF) * HID + t] + g_etab[(p0 >> 16) * HID + t];
        float vb = g_x[(p1 & 0xFFFF) * HID + t] + g_etab[(p1 >> 16) * HID + t];
        acc += fmaxf(va, 0.f) + fmaxf(vb, 0.f);
    }
    if (k < s1) {
        int p = g_packed[k];
        float v = g_x[(p & 0xFFFF) * HID + t] + g_etab[(p >> 16) * HID + t];
        acc += fmaxf(v, 0.f);
    }
    g_h[n * HID + t] = acc;
}

// ---------------- TF32 tensor-core GEMM ----------------
// C[M,200] = relu(epilogue(A[M,200] @ B[200,200]))
// MODE 0: A=g_h, C=g_t, epilogue = v*alpha[col]+beta[col]   (Linear1 + folded BN)
// MODE 1: A=g_t, C=g_x, epilogue = v + bias[col]            (Linear2 + bias)
// BM=128, BN=200 (full), BK=16, 8 warps; warp w owns rows [16w,16w+16),
// 25 n-tiles of 8 -> 100 fp32 accumulators per thread. mma.m16n8k8 tf32.

__device__ __forceinline__ uint32_t f2tf32(float f) {
    uint32_t r;
    asm("cvt.rna.tf32.f32 %0, %1;" : "=r"(r) : "f"(f));
    return r;
}

__device__ __forceinline__ void mma_tf32(float* c, uint32_t a0, uint32_t a1,
                                         uint32_t a2, uint32_t a3,
                                         uint32_t b0, uint32_t b1) {
    asm volatile(
        "mma.sync.aligned.m16n8k8.row.col.f32.tf32.tf32.f32 "
        "{%0,%1,%2,%3}, {%4,%5,%6,%7}, {%8,%9}, {%0,%1,%2,%3};\n"
        : "+f"(c[0]), "+f"(c[1]), "+f"(c[2]), "+f"(c[3])
        : "r"(a0), "r"(a1), "r"(a2), "r"(a3), "r"(b0), "r"(b1));
}

template <int MODE>
__global__ void __launch_bounds__(256, 1) gemm_tc_kernel(const float* __restrict__ B,
                                                         const float* __restrict__ bias,
                                                         int layer) {
    const float* __restrict__ A = (MODE == 0) ? g_h : g_t;
    float* __restrict__ C = (MODE == 0) ? g_t : g_x;

    __shared__ uint32_t As[16][136];   // [k][row], stride 136 -> conflict-free frag loads
    __shared__ uint32_t Bs[16][200];   // [k][n],   stride 200 (==8 mod 32) conflict-free

    const int tid = threadIdx.x;
    const int warp = tid >> 5;
    const int lane = tid & 31;
    const int row0 = blockIdx.x * 128;
    const int grp = lane >> 2;      // 0..7
    const int qid = lane & 3;       // 0..3

    float acc[25][4];
#pragma unroll
    for (int nt = 0; nt < 25; nt++)
#pragma unroll
        for (int j = 0; j < 4; j++) acc[nt][j] = 0.f;

    for (int k0 = 0; k0 < HID; k0 += 16) {
        // ---- load A tile: 128 rows x 16 k = 512 float4 ----
#pragma unroll
        for (int it = 0; it < 2; it++) {
            int i = tid + it * 256;
            int r = i >> 2;
            int c = (i & 3) * 4;
            int gr = row0 + r, gk = k0 + c;
            float4 v = make_float4(0.f, 0.f, 0.f, 0.f);
            if (gr < N_NODESC && gk + 3 < HID)
                v = *(const float4*)(A + (size_t)gr * HID + gk);
            As[c + 0][r] = f2tf32(v.x);
            As[c + 1][r] = f2tf32(v.y);
            As[c + 2][r] = f2tf32(v.z);
            As[c + 3][r] = f2tf32(v.w);
        }
        // ---- load B tile: 16 k x 200 n = 800 float4 ----
        for (int i = tid; i < 800; i += 256) {
            int kk = i / 50;
            int c = (i % 50) * 4;
            int gk = k0 + kk;
            float4 v = make_float4(0.f, 0.f, 0.f, 0.f);
            if (gk < HID)
                v = *(const float4*)(B + (size_t)gk * HID + c);
            uint4 t4;
            t4.x = f2tf32(v.x); t4.y = f2tf32(v.y);
            t4.z = f2tf32(v.z); t4.w = f2tf32(v.w);
            *(uint4*)&Bs[kk][c] = t4;
        }
        __syncthreads();

#pragma unroll
        for (int ks = 0; ks < 16; ks += 8) {
            int ar = warp * 16 + grp;
            int ak = ks + qid;
            uint32_t a0 = As[ak][ar];
            uint32_t a1 = As[ak][ar + 8];
            uint32_t a2 = As[ak + 4][ar];
            uint32_t a3 = As[ak + 4][ar + 8];
#pragma unroll
            for (int nt = 0; nt < 25; nt++) {
                int n = nt * 8 + grp;
                uint32_t b0 = Bs[ks + qid][n];
                uint32_t b1 = Bs[ks + qid + 4][n];
                mma_tf32(acc[nt], a0, a1, a2, a3, b0, b1);
            }
        }
        __syncthreads();
    }

    // ---- epilogue ----
    int r = row0 + warp * 16 + grp;
    bool ok0 = r < N_NODESC;
    bool ok1 = (r + 8) < N_NODESC;
    const float* abase = g_alpha + layer * HID;
    const float* bbase = g_beta + layer * HID;
#pragma unroll
    for (int nt = 0; nt < 25; nt++) {
        int col = nt * 8 + 2 * qid;
        float v0 = acc[nt][0], v1 = acc[nt][1];
        float v2 = acc[nt][2], v3 = acc[nt][3];
        if (MODE == 0) {
            float a0 = abase[col], a1 = abase[col + 1];
            float bb0 = bbase[col], bb1 = bbase[col + 1];
            v0 = v0 * a0 + bb0; v1 = v1 * a1 + bb1;
            v2 = v2 * a0 + bb0; v3 = v3 * a1 + bb1;
        } else {
            float bi0 = bias[col], bi1 = bias[col + 1];
            v0 += bi0; v1 += bi1; v2 += bi0; v3 += bi1;
        }
        if (ok0) {
            float2 w = make_float2(fmaxf(v0, 0.f), fmaxf(v1, 0.f));
            *(float2*)(C + (size_t)r * HID + col) = w;
        }
        if (ok1) {
            float2 w = make_float2(fmaxf(v2, 0.f), fmaxf(v3, 0.f));
            *(float2*)(C + (size_t)(r + 8) * HID + col) = w;
        }
    }
}

// run-accumulated segment-sum pooling over sorted batch_vec
__global__ void pool_kernel(const int* __restrict__ batch, int layer) {
    int t = threadIdx.x;
    if (t >= HID) return;
    int i0 = blockIdx.x * 64;
    int i1 = i0 + 64; if (i1 > N_NODESC) i1 = N_NODESC;
    if (i0 >= N_NODESC) return;
    float* pooled = g_pooled + layer * NG * HID;
    float acc = 0.f;
    int cur = batch[i0];
    for (int i = i0; i < i1; i++) {
        int g = batch[i];
        if (g != cur) { atomicAdd(&pooled[cur * HID + t], acc); acc = 0.f; cur = g; }
        acc += g_x[i * HID + t];
    }
    atomicAdd(&pooled[cur * HID + t], acc);
}

__global__ void final_kernel(const float* __restrict__ fcW, const float* __restrict__ fcb,
                             float* __restrict__ out) {
    __shared__ float red[256];
    int g = blockIdx.x;
    int t = threadIdx.x;
    int o = t & 15, seg = t >> 4;
    float acc = 0.f;
    for (int i = 0; i < NL + 1; i++) {
        const float* p = g_pooled + (i * NG + g) * HID;
        const float* w = fcW + i * HID * NOUT;
        for (int tt = seg; tt < HID; tt += 16)
            acc += p[tt] * w[tt * NOUT + o];
    }
    red[t] = acc;
    __syncthreads();
    for (int s = 8; s >= 1; s >>= 1) {
        if (seg < s) red[t] += red[t + s * 16];
        __syncthreads();
    }
    if (seg == 0) {
        float bias = 0.f;
        for (int i = 0; i < NL + 1; i++) bias += fcb[i * NOUT + o];
        float cnt = fmaxf((float)g_counts[g], 1.f);
        out[g * NOUT + o] = red[o] / cnt + bias;
    }
}

// ---------------- launch ----------------
extern "C" void kernel_launch(void* const* d_in, const int* in_sizes, int n_in,
                              void* d_out, int out_size) {
    (void)in_sizes; (void)n_in; (void)out_size;
    const int* node_kind    = (const int*)d_in[0];
    const int* node_content = (const int*)d_in[1];
    const int* edge_index   = (const int*)d_in[2];
    const int* edge_type    = (const int*)d_in[3];
    const int* edge_pos     = (const int*)d_in[4];
    const int* batch_vec    = (const int*)d_in[5];
    const float* kind_emb   = (const float*)d_in[6];
    const float* inst2vec   = (const float*)d_in[7];
    const float* type_emb   = (const float*)d_in[8];
    const float* etype_emb  = (const float*)d_in[9];
    const float* epos_emb   = (const float*)d_in[10];
    const float* W1         = (const float*)d_in[11];
    const float* b1         = (const float*)d_in[12];
    const float* bn_g       = (const float*)d_in[13];
    const float* bn_b       = (const float*)d_in[14];
    const float* bn_m       = (const float*)d_in[15];
    const float* bn_v       = (const float*)d_in[16];
    const float* W2         = (const float*)d_in[17];
    const float* b2         = (const float*)d_in[18];
    const float* fc_W       = (const float*)d_in[19];
    const float* fc_b       = (const float*)d_in[20];
    float* out = (float*)d_out;

    const int* src = edge_index;
    const int* dst = edge_index + N_EDGESC;

    zero_scratch<<<(N_NODESC + 255) / 256, 256>>>();
    node_emb_kernel<<<N_NODESC, 256>>>(node_kind, node_content, kind_emb, inst2vec, type_emb);
    etab_kernel<<<(60 * HID + 255) / 256, 256>>>(etype_emb, epos_emb);
    bnfold_kernel<<<(NL * HID + 255) / 256, 256>>>(bn_g, bn_b, bn_m, bn_v, b1);

    hist_kernel<<<(N_EDGESC + 255) / 256, 256>>>(dst);
    scan_kernel<<<1, 1024>>>();
    scatter_kernel<<<(N_EDGESC + 255) / 256, 256>>>(src, dst, edge_type, edge_pos);
    counts_kernel<<<(N_NODESC + 255) / 256, 256>>>(batch_vec);

    int ggrid = (N_NODESC + 127) / 128;
    pool_kernel<<<(N_NODESC + 63) / 64, 256>>>(batch_vec, 0);
    for (int l = 0; l < NL; l++) {
        aggregate_kernel<<<N_NODESC, 256>>>();
        gemm_tc_kernel<0><<<ggrid, 256>>>(W1 + l * HID * HID, nullptr, l);
        gemm_tc_kernel<1><<<ggrid, 256>>>(W2 + l * HID * HID, b2 + l * HID, l);
        pool_kernel<<<(N_NODESC + 63) / 64, 256>>>(batch_vec, l + 1);
    }
    final_kernel<<<NG, 256>>>(fc_W, fc_b, out);
}

// round 5
// speedup vs baseline: 1.6891x; 1.3438x over previous
#include <cuda_runtime.h>
#include <cstdint>

#define N_NODESC 50000
#define N_EDGESC 400000
#define HID 200
#define HID4 50
#define NG 64
#define NOUT 16
#define NL 5

// ---------------- scratch (static __device__, no allocation) ----------------
static __device__ float g_x[N_NODESC * HID];   // current node features
static __device__ float g_h[N_NODESC * HID];   // x + aggregated messages
static __device__ float g_t[N_NODESC * HID];   // intermediate after GEMM1
static __device__ float g_etab[60 * HID];      // etype(3) x epos(20) edge embedding table
static __device__ float g_alpha[NL * HID];     // folded BN scale
static __device__ float g_beta[NL * HID];      // folded BN shift (incl. b1)
static __device__ int   g_deg[N_NODESC];
static __device__ int   g_off[N_NODESC + 1];
static __device__ int   g_cur[N_NODESC];
static __device__ int   g_packed[N_EDGESC];    // src | (eidx<<16)
static __device__ float g_pooled[(NL + 1) * NG * HID];
static __device__ int   g_counts[NG];

// ---------------- small setup kernels ----------------
__global__ void zero_scratch() {
    int i = blockIdx.x * blockDim.x + threadIdx.x;
    if (i < N_NODESC) { g_deg[i] = 0; g_cur[i] = 0; }
    if (i < NG) g_counts[i] = 0;
    int stride = gridDim.x * blockDim.x;
    for (int j = i; j < (NL + 1) * NG * HID; j += stride) g_pooled[j] = 0.f;
}

__global__ void node_emb_kernel(const int* __restrict__ kind, const int* __restrict__ content,
                                const float* __restrict__ kemb, const float* __restrict__ i2v,
                                const float* __restrict__ temb) {
    int n = blockIdx.x * 4 + (threadIdx.x >> 6);
    int t = threadIdx.x & 63;
    if (t >= HID4 || n >= N_NODESC) return;
    int k = kind[n];
    const float4* k4 = (const float4*)(kemb + k * HID);
    float4 v = k4[t];
    float4 w;
    if (k == 0) w = ((const float4*)(i2v + content[n] * HID))[t];
    else        w = ((const float4*)temb)[t];
    v.x += w.x; v.y += w.y; v.z += w.z; v.w += w.w;
    ((float4*)g_x)[n * HID4 + t] = v;
}

__global__ void etab_kernel(const float* __restrict__ etype_emb, const float* __restrict__ epos_emb) {
    int idx = blockIdx.x * blockDim.x + threadIdx.x;
    if (idx >= 60 * HID) return;
    int e = idx / HID, t = idx % HID;
    g_etab[idx] = etype_emb[(e / 20) * HID + t] + epos_emb[(e % 20) * HID + t];
}

__global__ void bnfold_kernel(const float* __restrict__ bn_g, const float* __restrict__ bn_b,
                              const float* __restrict__ bn_m, const float* __restrict__ bn_v,
                              const float* __restrict__ b1) {
    int idx = blockIdx.x * blockDim.x + threadIdx.x;
    if (idx >= NL * HID) return;
    float a = bn_g[idx] * rsqrtf(bn_v[idx] + 1e-5f);
    g_alpha[idx] = a;
    g_beta[idx] = (b1[idx] - bn_m[idx]) * a + bn_b[idx];
}

// ---------------- CSR build (counting sort by dst) ----------------
__global__ void hist_kernel(const int* __restrict__ dst) {
    int j = blockIdx.x * blockDim.x + threadIdx.x;
    if (j < N_EDGESC) atomicAdd(&g_deg[dst[j]], 1);
}

__global__ void scan_kernel() {
    __shared__ int s[1024];
    __shared__ int carry;
    int lt = threadIdx.x;
    if (lt == 0) carry = 0;
    __syncthreads();
    for (int base = 0; base < N_NODESC; base += 1024) {
        int i = base + lt;
        int v = (i < N_NODESC) ? g_deg[i] : 0;
        s[lt] = v;
        __syncthreads();
        for (int ofs = 1; ofs < 1024; ofs <<= 1) {
            int tv = (lt >= ofs) ? s[lt - ofs] : 0;
            __syncthreads();
            s[lt] += tv;
            __syncthreads();
        }
        if (i < N_NODESC) g_off[i + 1] = carry + s[lt];
        int total = s[1023];
        __syncthreads();
        if (lt == 0) carry += total;
        __syncthreads();
    }
    if (threadIdx.x == 0) g_off[0] = 0;
}

__global__ void scatter_kernel(const int* __restrict__ src, const int* __restrict__ dst,
                               const int* __restrict__ etype, const int* __restrict__ epos) {
    int j = blockIdx.x * blockDim.x + threadIdx.x;
    if (j >= N_EDGESC) return;
    int d = dst[j];
    int pos = g_off[d] + atomicAdd(&g_cur[d], 1);
    int ep = epos[j]; if (ep > 19) ep = 19;
    int ei = etype[j] * 20 + ep;
    g_packed[pos] = src[j] | (ei << 16);
}

__global__ void counts_kernel(const int* __restrict__ batch) {
    int i = blockIdx.x * blockDim.x + threadIdx.x;
    if (i < N_NODESC) atomicAdd(&g_counts[batch[i]], 1);
}

// ---------------- per-layer kernels ----------------
// h[n] = x[n] + sum_{edges into n} relu(x[src] + etab[eidx])
// float4 lanes (50 active of 64), 4-way edge unroll for MLP.
__device__ __forceinline__ float4 relu_add4(float4 a, float4 b) {
    float4 r;
    r.x = fmaxf(a.x + b.x, 0.f); r.y = fmaxf(a.y + b.y, 0.f);
    r.z = fmaxf(a.z + b.z, 0.f); r.w = fmaxf(a.w + b.w, 0.f);
    return r;
}
__device__ __forceinline__ void acc4(float4& a, float4 b) {
    a.x += b.x; a.y += b.y; a.z += b.z; a.w += b.w;
}

__global__ void __launch_bounds__(64) aggregate_kernel() {
    int n = blockIdx.x;
    int t = threadIdx.x;
    if (t >= HID4) return;
    const float4* __restrict__ x4 = (const float4*)g_x;
    const float4* __restrict__ e4 = (const float4*)g_etab;
    float4 acc = x4[n * HID4 + t];
    int s0 = g_off[n], s1 = g_off[n + 1];
    int k = s0;
    for (; k + 3 < s1; k += 4) {
        int p0 = g_packed[k], p1 = g_packed[k + 1];
        int p2 = g_packed[k + 2], p3 = g_packed[k + 3];
        float4 a0 = x4[(p0 & 0xFFFF) * HID4 + t];
        float4 b0 = e4[(p0 >> 16) * HID4 + t];
        float4 a1 = x4[(p1 & 0xFFFF) * HID4 + t];
        float4 b1 = e4[(p1 >> 16) * HID4 + t];
        float4 a2 = x4[(p2 & 0xFFFF) * HID4 + t];
        float4 b2 = e4[(p2 >> 16) * HID4 + t];
        float4 a3 = x4[(p3 & 0xFFFF) * HID4 + t];
        float4 b3 = e4[(p3 >> 16) * HID4 + t];
        acc4(acc, relu_add4(a0, b0));
        acc4(acc, relu_add4(a1, b1));
        acc4(acc, relu_add4(a2, b2));
        acc4(acc, relu_add4(a3, b3));
    }
    for (; k < s1; k++) {
        int p = g_packed[k];
        acc4(acc, relu_add4(x4[(p & 0xFFFF) * HID4 + t], e4[(p >> 16) * HID4 + t]));
    }
    ((float4*)g_h)[n * HID4 + t] = acc;
}

// ---------------- TF32 tensor-core GEMM ----------------
// C[M,200] = relu(epilogue(A[M,200] @ B[200,200]))
// grid = (ceil(M/128), 2): y=0 -> cols 0..103 (13 n-tiles), y=1 -> cols 104..199 (12 tiles)
// 8 warps, warp w owns rows [16w,16w+16). acc <= 13*4 = 52 regs -> 2 CTAs/SM.

__device__ __forceinline__ uint32_t f2tf32(float f) {
    uint32_t r;
    asm("cvt.rna.tf32.f32 %0, %1;" : "=r"(r) : "f"(f));
    return r;
}

__device__ __forceinline__ void mma_tf32(float* c, uint32_t a0, uint32_t a1,
                                         uint32_t a2, uint32_t a3,
                                         uint32_t b0, uint32_t b1) {
    asm volatile(
        "mma.sync.aligned.m16n8k8.row.col.f32.tf32.tf32.f32 "
        "{%0,%1,%2,%3}, {%4,%5,%6,%7}, {%8,%9}, {%0,%1,%2,%3};\n"
        : "+f"(c[0]), "+f"(c[1]), "+f"(c[2]), "+f"(c[3])
        : "r"(a0), "r"(a1), "r"(a2), "r"(a3), "r"(b0), "r"(b1));
}

template <int MODE>
__global__ void __launch_bounds__(256, 2) gemm_tc_kernel(const float* __restrict__ B,
                                                         const float* __restrict__ bias,
                                                         int layer) {
    const float* __restrict__ A = (MODE == 0) ? g_h : g_t;
    float* __restrict__ C = (MODE == 0) ? g_t : g_x;

    __shared__ uint32_t As[16][136];   // [k][row], stride 136 (=8 mod 32) conflict-free
    __shared__ uint32_t Bs[16][104];   // [k][n],   stride 104 (=8 mod 32) conflict-free

    const int tid = threadIdx.x;
    const int warp = tid >> 5;
    const int lane = tid & 31;
    const int row0 = blockIdx.x * 128;
    const int col0 = blockIdx.y * 104;
    const int NT = (blockIdx.y == 0) ? 13 : 12;      // n-tiles of 8
    const int NC4 = NT * 2;                           // float4 cols per k-row

    float acc[13][4];
#pragma unroll
    for (int nt = 0; nt < 13; nt++)
#pragma unroll
        for (int j = 0; j < 4; j++) acc[nt][j] = 0.f;

    for (int k0 = 0; k0 < HID; k0 += 16) {
        // ---- A tile: 128 rows x 16 k ----
#pragma unroll
        for (int it = 0; it < 2; it++) {
            int i = tid + it * 256;
            int r = i >> 2;
            int c = (i & 3) * 4;
            int gr = row0 + r, gk = k0 + c;
            float4 v = make_float4(0.f, 0.f, 0.f, 0.f);
            if (gr < N_NODESC && gk + 3 < HID)
                v = *(const float4*)(A + (size_t)gr * HID + gk);
            As[c + 0][r] = f2tf32(v.x);
            As[c + 1][r] = f2tf32(v.y);
            As[c + 2][r] = f2tf32(v.z);
            As[c + 3][r] = f2tf32(v.w);
        }
        // ---- B tile: 16 k x (NT*8) n ----
        for (int i = tid; i < 16 * NC4; i += 256) {
            int kk = i / NC4;
            int c = (i % NC4) * 4;
            int gk = k0 + kk;
            float4 v = make_float4(0.f, 0.f, 0.f, 0.f);
            if (gk < HID)
                v = *(const float4*)(B + (size_t)gk * HID + col0 + c);
            uint4 t4;
            t4.x = f2tf32(v.x); t4.y = f2tf32(v.y);
            t4.z = f2tf32(v.z); t4.w = f2tf32(v.w);
            *(uint4*)&Bs[kk][c] = t4;
        }
        __syncthreads();

        const int grp = lane >> 2;
        const int qid = lane & 3;
        const int ar = warp * 16 + grp;
#pragma unroll
        for (int ks = 0; ks < 16; ks += 8) {
            int ak = ks + qid;
            uint32_t a0 = As[ak][ar];
            uint32_t a1 = As[ak][ar + 8];
            uint32_t a2 = As[ak + 4][ar];
            uint32_t a3 = As[ak + 4][ar + 8];
#pragma unroll
            for (int nt = 0; nt < 13; nt++) {
                if (nt < NT) {
                    int n = nt * 8 + grp;
                    uint32_t b0 = Bs[ks + qid][n];
                    uint32_t b1 = Bs[ks + qid + 4][n];
                    mma_tf32(acc[nt], a0, a1, a2, a3, b0, b1);
                }
            }
        }
        __syncthreads();
    }

    // ---- epilogue ----
    const int grp = lane >> 2;
    const int qid = lane & 3;
    int r = row0 + warp * 16 + grp;
    bool ok0 = r < N_NODESC;
    bool ok1 = (r + 8) < N_NODESC;
    const float* abase = g_alpha + layer * HID;
    const float* bbase = g_beta + layer * HID;
#pragma unroll
    for (int nt = 0; nt < 13; nt++) {
        if (nt < NT) {
            int col = col0 + nt * 8 + 2 * qid;
            float v0 = acc[nt][0], v1 = acc[nt][1];
            float v2 = acc[nt][2], v3 = acc[nt][3];
            if (MODE == 0) {
                float a0 = abase[col], a1 = abase[col + 1];
                float bb0 = bbase[col], bb1 = bbase[col + 1];
                v0 = v0 * a0 + bb0; v1 = v1 * a1 + bb1;
                v2 = v2 * a0 + bb0; v3 = v3 * a1 + bb1;
            } else {
                float bi0 = bias[col], bi1 = bias[col + 1];
                v0 += bi0; v1 += bi1; v2 += bi0; v3 += bi1;
            }
            if (ok0) {
                float2 w = make_float2(fmaxf(v0, 0.f), fmaxf(v1, 0.f));
                *(float2*)(C + (size_t)r * HID + col) = w;
            }
            if (ok1) {
                float2 w = make_float2(fmaxf(v2, 0.f), fmaxf(v3, 0.f));
                *(float2*)(C + (size_t)(r + 8) * HID + col) = w;
            }
        }
    }
}

// run-accumulated segment-sum pooling over sorted batch_vec (float4 lanes)
__global__ void __launch_bounds__(64) pool_kernel(const int* __restrict__ batch, int layer) {
    int t = threadIdx.x;
    if (t >= HID4) return;
    int i0 = blockIdx.x * 64;
    int i1 = i0 + 64; if (i1 > N_NODESC) i1 = N_NODESC;
    if (i0 >= N_NODESC) return;
    const float4* __restrict__ x4 = (const float4*)g_x;
    float* pooled = g_pooled + layer * NG * HID;
    float4 acc = make_float4(0.f, 0.f, 0.f, 0.f);
    int cur = batch[i0];
    for (int i = i0; i < i1; i++) {
        int g = batch[i];
        if (g != cur) {
            float* p = pooled + cur * HID + t * 4;
            atomicAdd(p + 0, acc.x); atomicAdd(p + 1, acc.y);
            atomicAdd(p + 2, acc.z); atomicAdd(p + 3, acc.w);
            acc = make_float4(0.f, 0.f, 0.f, 0.f);
            cur = g;
        }
        acc4(acc, x4[i * HID4 + t]);
    }
    float* p = pooled + cur * HID + t * 4;
    atomicAdd(p + 0, acc.x); atomicAdd(p + 1, acc.y);
    atomicAdd(p + 2, acc.z); atomicAdd(p + 3, acc.w);
}

__global__ void final_kernel(const float* __restrict__ fcW, const float* __restrict__ fcb,
                             float* __restrict__ out) {
    __shared__ float red[256];
    int g = blockIdx.x;
    int t = threadIdx.x;
    int o = t & 15, seg = t >> 4;
    float acc = 0.f;
    for (int i = 0; i < NL + 1; i++) {
        const float* p = g_pooled + (i * NG + g) * HID;
        const float* w = fcW + i * HID * NOUT;
        for (int tt = seg; tt < HID; tt += 16)
            acc += p[tt] * w[tt * NOUT + o];
    }
    red[t] = acc;
    __syncthreads();
    for (int s = 8; s >= 1; s >>= 1) {
        if (seg < s) red[t] += red[t + s * 16];
        __syncthreads();
    }
    if (seg == 0) {
        float bias = 0.f;
        for (int i = 0; i < NL + 1; i++) bias += fcb[i * NOUT + o];
        float cnt = fmaxf((float)g_counts[g], 1.f);
        out[g * NOUT + o] = red[o] / cnt + bias;
    }
}

// ---------------- launch ----------------
extern "C" void kernel_launch(void* const* d_in, const int* in_sizes, int n_in,
                              void* d_out, int out_size) {
    (void)in_sizes; (void)n_in; (void)out_size;
    const int* node_kind    = (const int*)d_in[0];
    const int* node_content = (const int*)d_in[1];
    const int* edge_index   = (const int*)d_in[2];
    const int* edge_type    = (const int*)d_in[3];
    const int* edge_pos     = (const int*)d_in[4];
    const int* batch_vec    = (const int*)d_in[5];
    const float* kind_emb   = (const float*)d_in[6];
    const float* inst2vec   = (const float*)d_in[7];
    const float* type_emb   = (const float*)d_in[8];
    const float* etype_emb  = (const float*)d_in[9];
    const float* epos_emb   = (const float*)d_in[10];
    const float* W1         = (const float*)d_in[11];
    const float* b1         = (const float*)d_in[12];
    const float* bn_g       = (const float*)d_in[13];
    const float* bn_b       = (const float*)d_in[14];
    const float* bn_m       = (const float*)d_in[15];
    const float* bn_v       = (const float*)d_in[16];
    const float* W2         = (const float*)d_in[17];
    const float* b2         = (const float*)d_in[18];
    const float* fc_W       = (const float*)d_in[19];
    const float* fc_b       = (const float*)d_in[20];
    float* out = (float*)d_out;

    const int* src = edge_index;
    const int* dst = edge_index + N_EDGESC;

    zero_scratch<<<(N_NODESC + 255) / 256, 256>>>();
    node_emb_kernel<<<(N_NODESC + 3) / 4, 256>>>(node_kind, node_content, kind_emb, inst2vec, type_emb);
    etab_kernel<<<(60 * HID + 255) / 256, 256>>>(etype_emb, epos_emb);
    bnfold_kernel<<<(NL * HID + 255) / 256, 256>>>(bn_g, bn_b, bn_m, bn_v, b1);

    hist_kernel<<<(N_EDGESC + 255) / 256, 256>>>(dst);
    scan_kernel<<<1, 1024>>>();
    scatter_kernel<<<(N_EDGESC + 255) / 256, 256>>>(src, dst, edge_type, edge_pos);
    counts_kernel<<<(N_NODESC + 255) / 256, 256>>>(batch_vec);

    dim3 ggrid((N_NODESC + 127) / 128, 2);
    pool_kernel<<<(N_NODESC + 63) / 64, 64>>>(batch_vec, 0);
    for (int l = 0; l < NL; l++) {
        aggregate_kernel<<<N_NODESC, 64>>>();
        gemm_tc_kernel<0><<<ggrid, 256>>>(W1 + l * HID * HID, nullptr, l);
        gemm_tc_kernel<1><<<ggrid, 256>>>(W2 + l * HID * HID, b2 + l * HID, l);
        pool_kernel<<<(N_NODESC + 63) / 64, 64>>>(batch_vec, l + 1);
    }
    final_kernel<<<NG, 256>>>(fc_W, fc_b, out);
}

// round 6
// speedup vs baseline: 2.1506x; 1.2732x over previous
#include <cuda_runtime.h>
#include <cstdint>

#define N_NODESC 50000
#define N_EDGESC 400000
#define HID 200
#define HID4 50
#define NG 64
#define NOUT 16
#define NL 5

// ---------------- scratch (static __device__, no allocation) ----------------
static __device__ float g_x[N_NODESC * HID];   // current node features
static __device__ float g_h[N_NODESC * HID];   // x + aggregated messages
static __device__ float g_t[N_NODESC * HID];   // intermediate after GEMM1
static __device__ float g_etab[60 * HID];      // etype(3) x epos(20) edge embedding table
static __device__ float g_alpha[NL * HID];     // folded BN scale
static __device__ float g_beta[NL * HID];      // folded BN shift (incl. b1)
static __device__ int   g_deg[N_NODESC];
static __device__ int   g_off[N_NODESC + 1];
static __device__ int   g_cur[N_NODESC];
static __device__ int   g_packed[N_EDGESC];    // src | (eidx<<16)
static __device__ float g_pooled[(NL + 1) * NG * HID];
static __device__ int   g_counts[NG];

// ---------------- small setup kernels ----------------
__global__ void zero_scratch() {
    int i = blockIdx.x * blockDim.x + threadIdx.x;
    if (i < N_NODESC) { g_deg[i] = 0; g_cur[i] = 0; }
    if (i < NG) g_counts[i] = 0;
    int stride = gridDim.x * blockDim.x;
    for (int j = i; j < (NL + 1) * NG * HID; j += stride) g_pooled[j] = 0.f;
}

__global__ void node_emb_kernel(const int* __restrict__ kind, const int* __restrict__ content,
                                const float* __restrict__ kemb, const float* __restrict__ i2v,
                                const float* __restrict__ temb) {
    int n = blockIdx.x * 4 + (threadIdx.x >> 6);
    int t = threadIdx.x & 63;
    if (t >= HID4 || n >= N_NODESC) return;
    int k = kind[n];
    const float4* k4 = (const float4*)(kemb + k * HID);
    float4 v = k4[t];
    float4 w;
    if (k == 0) w = ((const float4*)(i2v + content[n] * HID))[t];
    else        w = ((const float4*)temb)[t];
    v.x += w.x; v.y += w.y; v.z += w.z; v.w += w.w;
    ((float4*)g_x)[n * HID4 + t] = v;
}

__global__ void etab_kernel(const float* __restrict__ etype_emb, const float* __restrict__ epos_emb) {
    int idx = blockIdx.x * blockDim.x + threadIdx.x;
    if (idx >= 60 * HID) return;
    int e = idx / HID, t = idx % HID;
    g_etab[idx] = etype_emb[(e / 20) * HID + t] + epos_emb[(e % 20) * HID + t];
}

__global__ void bnfold_kernel(const float* __restrict__ bn_g, const float* __restrict__ bn_b,
                              const float* __restrict__ bn_m, const float* __restrict__ bn_v,
                              const float* __restrict__ b1) {
    int idx = blockIdx.x * blockDim.x + threadIdx.x;
    if (idx >= NL * HID) return;
    float a = bn_g[idx] * rsqrtf(bn_v[idx] + 1e-5f);
    g_alpha[idx] = a;
    g_beta[idx] = (b1[idx] - bn_m[idx]) * a + bn_b[idx];
}

// ---------------- CSR build (counting sort by dst) ----------------
__global__ void hist_kernel(const int* __restrict__ dst) {
    int j = blockIdx.x * blockDim.x + threadIdx.x;
    if (j < N_EDGESC) atomicAdd(&g_deg[dst[j]], 1);
}

__global__ void scan_kernel() {
    __shared__ int s[1024];
    __shared__ int carry;
    int lt = threadIdx.x;
    if (lt == 0) carry = 0;
    __syncthreads();
    for (int base = 0; base < N_NODESC; base += 1024) {
        int i = base + lt;
        int v = (i < N_NODESC) ? g_deg[i] : 0;
        s[lt] = v;
        __syncthreads();
        for (int ofs = 1; ofs < 1024; ofs <<= 1) {
            int tv = (lt >= ofs) ? s[lt - ofs] : 0;
            __syncthreads();
            s[lt] += tv;
            __syncthreads();
        }
        if (i < N_NODESC) g_off[i + 1] = carry + s[lt];
        int total = s[1023];
        __syncthreads();
        if (lt == 0) carry += total;
        __syncthreads();
    }
    if (threadIdx.x == 0) g_off[0] = 0;
}

__global__ void scatter_kernel(const int* __restrict__ src, const int* __restrict__ dst,
                               const int* __restrict__ etype, const int* __restrict__ epos) {
    int j = blockIdx.x * blockDim.x + threadIdx.x;
    if (j >= N_EDGESC) return;
    int d = dst[j];
    int pos = g_off[d] + atomicAdd(&g_cur[d], 1);
    int ep = epos[j]; if (ep > 19) ep = 19;
    int ei = etype[j] * 20 + ep;
    g_packed[pos] = src[j] | (ei << 16);
}

__global__ void counts_kernel(const int* __restrict__ batch) {
    int i = blockIdx.x * blockDim.x + threadIdx.x;
    if (i < N_NODESC) atomicAdd(&g_counts[batch[i]], 1);
}

// ---------------- per-layer kernels ----------------
__device__ __forceinline__ float4 relu_add4(float4 a, float4 b) {
    float4 r;
    r.x = fmaxf(a.x + b.x, 0.f); r.y = fmaxf(a.y + b.y, 0.f);
    r.z = fmaxf(a.z + b.z, 0.f); r.w = fmaxf(a.w + b.w, 0.f);
    return r;
}
__device__ __forceinline__ void acc4(float4& a, float4 b) {
    a.x += b.x; a.y += b.y; a.z += b.z; a.w += b.w;
}

// h[n] = x[n] + sum_{edges into n} relu(x[src] + etab[eidx]); 4 nodes/block
__global__ void __launch_bounds__(256) aggregate_kernel() {
    int n = blockIdx.x * 4 + (threadIdx.x >> 6);
    int t = threadIdx.x & 63;
    if (t >= HID4 || n >= N_NODESC) return;
    const float4* __restrict__ x4 = (const float4*)g_x;
    const float4* __restrict__ e4 = (const float4*)g_etab;
    float4 acc = x4[n * HID4 + t];
    int s0 = g_off[n], s1 = g_off[n + 1];
    int k = s0;
    for (; k + 3 < s1; k += 4) {
        int p0 = g_packed[k], p1 = g_packed[k + 1];
        int p2 = g_packed[k + 2], p3 = g_packed[k + 3];
        float4 a0 = x4[(p0 & 0xFFFF) * HID4 + t];
        float4 b0 = e4[(p0 >> 16) * HID4 + t];
        float4 a1 = x4[(p1 & 0xFFFF) * HID4 + t];
        float4 b1 = e4[(p1 >> 16) * HID4 + t];
        float4 a2 = x4[(p2 & 0xFFFF) * HID4 + t];
        float4 b2 = e4[(p2 >> 16) * HID4 + t];
        float4 a3 = x4[(p3 & 0xFFFF) * HID4 + t];
        float4 b3 = e4[(p3 >> 16) * HID4 + t];
        acc4(acc, relu_add4(a0, b0));
        acc4(acc, relu_add4(a1, b1));
        acc4(acc, relu_add4(a2, b2));
        acc4(acc, relu_add4(a3, b3));
    }
    for (; k < s1; k++) {
        int p = g_packed[k];
        acc4(acc, relu_add4(x4[(p & 0xFFFF) * HID4 + t], e4[(p >> 16) * HID4 + t]));
    }
    ((float4*)g_h)[n * HID4 + t] = acc;
}

// ---------------- FP16 tensor-core GEMM (m16n8k16) ----------------
// C[M,200] = relu(epilogue(A[M,200] @ B[200,200]))
// grid = (ceil(M/128), 2): y=0 -> cols 0..103 (NT=13), y=1 -> cols 104..199 (NT=12)
// 8 warps; warp w owns rows [16w,16w+16). K staged in 13 tiles of 16 (k=200 padded).
// Prefetch next tile into registers during MMA phase (LDG latency hidden).

__device__ __forceinline__ uint32_t pack_f16x2(float even, float odd) {
    // u32: lo half = even (first k), hi half = odd (second k)
    uint32_t r;
    asm("cvt.rn.f16x2.f32 %0, %1, %2;" : "=r"(r) : "f"(odd), "f"(even));
    return r;
}

__device__ __forceinline__ void mma_f16(float* c, uint32_t a0, uint32_t a1,
                                        uint32_t a2, uint32_t a3,
                                        uint32_t b0, uint32_t b1) {
    asm volatile(
        "mma.sync.aligned.m16n8k16.row.col.f32.f16.f16.f32 "
        "{%0,%1,%2,%3}, {%4,%5,%6,%7}, {%8,%9}, {%0,%1,%2,%3};\n"
        : "+f"(c[0]), "+f"(c[1]), "+f"(c[2]), "+f"(c[3])
        : "r"(a0), "r"(a1), "r"(a2), "r"(a3), "r"(b0), "r"(b1));
}

template <int MODE>
__global__ void __launch_bounds__(256, 2) gemm_tc_kernel(const float* __restrict__ B,
                                                         const float* __restrict__ bias,
                                                         int layer) {
    const float* __restrict__ A = (MODE == 0) ? g_h : g_t;
    float* __restrict__ C = (MODE == 0) ? g_t : g_x;

    // As[kk][row]: kk = k-pair index (0..7), u32 packs (2kk, 2kk+1). stride 136.
    // Bs[n][kk]:   u32 packs (B[2kk][n], B[2kk+1][n]). stride 12 -> conflict-free frags.
    __shared__ uint32_t As[8][136];
    __shared__ uint32_t Bs[104][12];

    const int tid = threadIdx.x;
    const int warp = tid >> 5;
    const int lane = tid & 31;
    const int grp = lane >> 2;      // 0..7
    const int qid = lane & 3;       // 0..3
    const int row0 = blockIdx.x * 128;
    const int col0 = blockIdx.y * 104;
    const int NT = (blockIdx.y == 0) ? 13 : 12;
    const int NC = NT * 8;
    const int ar = warp * 16 + grp;

    float acc[13][4];
#pragma unroll
    for (int nt = 0; nt < 13; nt++)
#pragma unroll
        for (int j = 0; j < 4; j++) acc[nt][j] = 0.f;

    // prefetch registers
    // A: thread covers (r = tid>>1 .. two halves? ) mapping: i in {tid, tid+256}? 128 rows x 8 u32
    //    use: r = tid >> 1, half = tid & 1 -> floats k0+8*half .. +7 (2 float4)
    float4 aR0, aR1;
    float bR[8];

    const int a_r = tid >> 1;          // 0..127
    const int a_half = tid & 1;        // 0..1
    const int a_gr = row0 + a_r;
    const bool a_ok = a_gr < N_NODESC;
    const float* aBase = A + (size_t)a_gr * HID;

    // ---- load tile 0 ----
    {
        int k0 = 0;
        int gk = k0 + a_half * 8;
        aR0 = make_float4(0.f, 0.f, 0.f, 0.f);
        aR1 = make_float4(0.f, 0.f, 0.f, 0.f);
        if (a_ok) {
            if (gk + 3 < HID)  aR0 = *(const float4*)(aBase + gk);
            if (gk + 7 < HID)  aR1 = *(const float4*)(aBase + gk + 4);
        }
#pragma unroll
        for (int j = 0; j < 4; j++) {
            int e = tid + j * 256;
            float v0 = 0.f, v1 = 0.f;
            if (e < 8 * NC) {
                int kk = e / NC, n = e - kk * NC;
                int g0 = k0 + 2 * kk;
                if (g0 < HID)     v0 = B[(size_t)g0 * HID + col0 + n];
                if (g0 + 1 < HID) v1 = B[(size_t)(g0 + 1) * HID + col0 + n];
            }
            bR[2 * j] = v0; bR[2 * j + 1] = v1;
        }
    }

    for (int t = 0; t < 13; t++) {
        // ---- store prefetched tile to smem ----
        {
            int kkb = a_half * 4;
            As[kkb + 0][a_r] = pack_f16x2(aR0.x, aR0.y);
            As[kkb + 1][a_r] = pack_f16x2(aR0.z, aR0.w);
            As[kkb + 2][a_r] = pack_f16x2(aR1.x, aR1.y);
            As[kkb + 3][a_r] = pack_f16x2(aR1.z, aR1.w);
#pragma unroll
            for (int j = 0; j < 4; j++) {
                int e = tid + j * 256;
                if (e < 8 * NC) {
                    int kk = e / NC, n = e - kk * NC;
                    Bs[n][kk] = pack_f16x2(bR[2 * j], bR[2 * j + 1]);
                }
            }
        }
        __syncthreads();

        // ---- issue next tile loads (latency hidden behind MMA) ----
        if (t + 1 < 13) {
            int k0 = (t + 1) * 16;
            int gk = k0 + a_half * 8;
            aR0 = make_float4(0.f, 0.f, 0.f, 0.f);
            aR1 = make_float4(0.f, 0.f, 0.f, 0.f);
            if (a_ok) {
                if (gk + 3 < HID)  aR0 = *(const float4*)(aBase + gk);
                if (gk + 7 < HID)  aR1 = *(const float4*)(aBase + gk + 4);
            }
#pragma unroll
            for (int j = 0; j < 4; j++) {
                int e = tid + j * 256;
                float v0 = 0.f, v1 = 0.f;
                if (e < 8 * NC) {
                    int kk = e / NC, n = e - kk * NC;
                    int g0 = k0 + 2 * kk;
                    if (g0 < HID)     v0 = B[(size_t)g0 * HID + col0 + n];
                    if (g0 + 1 < HID) v1 = B[(size_t)(g0 + 1) * HID + col0 + n];
                }
                bR[2 * j] = v0; bR[2 * j + 1] = v1;
            }
        }

        // ---- MMA phase: one m16n8k16 covers the whole 16-k tile ----
        {
            uint32_t a0 = As[qid][ar];
            uint32_t a1 = As[qid][ar + 8];
            uint32_t a2 = As[qid + 4][ar];
            uint32_t a3 = As[qid + 4][ar + 8];
#pragma unroll
            for (int nt = 0; nt < 13; nt++) {
                if (nt < NT) {
                    int n = nt * 8 + grp;
                    uint32_t b0 = Bs[n][qid];
                    uint32_t b1 = Bs[n][qid + 4];
                    mma_f16(acc[nt], a0, a1, a2, a3, b0, b1);
                }
            }
        }
        __syncthreads();
    }

    // ---- epilogue ----
    int r = row0 + warp * 16 + grp;
    bool ok0 = r < N_NODESC;
    bool ok1 = (r + 8) < N_NODESC;
    const float* abase = g_alpha + layer * HID;
    const float* bbase = g_beta + layer * HID;
#pragma unroll
    for (int nt = 0; nt < 13; nt++) {
        if (nt < NT) {
            int col = col0 + nt * 8 + 2 * qid;
            float v0 = acc[nt][0], v1 = acc[nt][1];
            float v2 = acc[nt][2], v3 = acc[nt][3];
            if (MODE == 0) {
                float a0 = abase[col], a1 = abase[col + 1];
                float bb0 = bbase[col], bb1 = bbase[col + 1];
                v0 = v0 * a0 + bb0; v1 = v1 * a1 + bb1;
                v2 = v2 * a0 + bb0; v3 = v3 * a1 + bb1;
            } else {
                float bi0 = bias[col], bi1 = bias[col + 1];
                v0 += bi0; v1 += bi1; v2 += bi0; v3 += bi1;
            }
            if (ok0) {
                float2 w = make_float2(fmaxf(v0, 0.f), fmaxf(v1, 0.f));
                *(float2*)(C + (size_t)r * HID + col) = w;
            }
            if (ok1) {
                float2 w = make_float2(fmaxf(v2, 0.f), fmaxf(v3, 0.f));
                *(float2*)(C + (size_t)(r + 8) * HID + col) = w;
            }
        }
    }
}

// run-accumulated segment-sum pooling over sorted batch_vec (float4 lanes)
__global__ void __launch_bounds__(64) pool_kernel(const int* __restrict__ batch, int layer) {
    int t = threadIdx.x;
    if (t >= HID4) return;
    int i0 = blockIdx.x * 64;
    int i1 = i0 + 64; if (i1 > N_NODESC) i1 = N_NODESC;
    if (i0 >= N_NODESC) return;
    const float4* __restrict__ x4 = (const float4*)g_x;
    float* pooled = g_pooled + layer * NG * HID;
    float4 acc = make_float4(0.f, 0.f, 0.f, 0.f);
    int cur = batch[i0];
    for (int i = i0; i < i1; i++) {
        int g = batch[i];
        if (g != cur) {
            float* p = pooled + cur * HID + t * 4;
            atomicAdd(p + 0, acc.x); atomicAdd(p + 1, acc.y);
            atomicAdd(p + 2, acc.z); atomicAdd(p + 3, acc.w);
            acc = make_float4(0.f, 0.f, 0.f, 0.f);
            cur = g;
        }
        acc4(acc, x4[i * HID4 + t]);
    }
    float* p = pooled + cur * HID + t * 4;
    atomicAdd(p + 0, acc.x); atomicAdd(p + 1, acc.y);
    atomicAdd(p + 2, acc.z); atomicAdd(p + 3, acc.w);
}

__global__ void final_kernel(const float* __restrict__ fcW, const float* __restrict__ fcb,
                             float* __restrict__ out) {
    __shared__ float red[256];
    int g = blockIdx.x;
    int t = threadIdx.x;
    int o = t & 15, seg = t >> 4;
    float acc = 0.f;
    for (int i = 0; i < NL + 1; i++) {
        const float* p = g_pooled + (i * NG + g) * HID;
        const float* w = fcW + i * HID * NOUT;
        for (int tt = seg; tt < HID; tt += 16)
            acc += p[tt] * w[tt * NOUT + o];
    }
    red[t] = acc;
    __syncthreads();
    for (int s = 8; s >= 1; s >>= 1) {
        if (seg < s) red[t] += red[t + s * 16];
        __syncthreads();
    }
    if (seg == 0) {
        float bias = 0.f;
        for (int i = 0; i < NL + 1; i++) bias += fcb[i * NOUT + o];
        float cnt = fmaxf((float)g_counts[g], 1.f);
        out[g * NOUT + o] = red[o] / cnt + bias;
    }
}

// ---------------- launch ----------------
extern "C" void kernel_launch(void* const* d_in, const int* in_sizes, int n_in,
                              void* d_out, int out_size) {
    (void)in_sizes; (void)n_in; (void)out_size;
    const int* node_kind    = (const int*)d_in[0];
    const int* node_content = (const int*)d_in[1];
    const int* edge_index   = (const int*)d_in[2];
    const int* edge_type    = (const int*)d_in[3];
    const int* edge_pos     = (const int*)d_in[4];
    const int* batch_vec    = (const int*)d_in[5];
    const float* kind_emb   = (const float*)d_in[6];
    const float* inst2vec   = (const float*)d_in[7];
    const float* type_emb   = (const float*)d_in[8];
    const float* etype_emb  = (const float*)d_in[9];
    const float* epos_emb   = (const float*)d_in[10];
    const float* W1         = (const float*)d_in[11];
    const float* b1         = (const float*)d_in[12];
    const float* bn_g       = (const float*)d_in[13];
    const float* bn_b       = (const float*)d_in[14];
    const float* bn_m       = (const float*)d_in[15];
    const float* bn_v       = (const float*)d_in[16];
    const float* W2         = (const float*)d_in[17];
    const float* b2         = (const float*)d_in[18];
    const float* fc_W       = (const float*)d_in[19];
    const float* fc_b       = (const float*)d_in[20];
    float* out = (float*)d_out;

    const int* src = edge_index;
    const int* dst = edge_index + N_EDGESC;

    zero_scratch<<<(N_NODESC + 255) / 256, 256>>>();
    node_emb_kernel<<<(N_NODESC + 3) / 4, 256>>>(node_kind, node_content, kind_emb, inst2vec, type_emb);
    etab_kernel<<<(60 * HID + 255) / 256, 256>>>(etype_emb, epos_emb);
    bnfold_kernel<<<(NL * HID + 255) / 256, 256>>>(bn_g, bn_b, bn_m, bn_v, b1);

    hist_kernel<<<(N_EDGESC + 255) / 256, 256>>>(dst);
    scan_kernel<<<1, 1024>>>();
    scatter_kernel<<<(N_EDGESC + 255) / 256, 256>>>(src, dst, edge_type, edge_pos);
    counts_kernel<<<(N_NODESC + 255) / 256, 256>>>(batch_vec);

    dim3 ggrid((N_NODESC + 127) / 128, 2);
    pool_kernel<<<(N_NODESC + 63) / 64, 64>>>(batch_vec, 0);
    for (int l = 0; l < NL; l++) {
        aggregate_kernel<<<(N_NODESC + 3) / 4, 256>>>();
        gemm_tc_kernel<0><<<ggrid, 256>>>(W1 + l * HID * HID, nullptr, l);
        gemm_tc_kernel<1><<<ggrid, 256>>>(W2 + l * HID * HID, b2 + l * HID, l);
        pool_kernel<<<(N_NODESC + 63) / 64, 64>>>(batch_vec, l + 1);
    }
    final_kernel<<<NG, 256>>>(fc_W, fc_b, out);
}

// round 7
// speedup vs baseline: 2.7873x; 1.2961x over previous
#include <cuda_runtime.h>
#include <cstdint>

#define N_NODESC 50000
#define N_EDGESC 400000
#define HID 200
#define HID4 50
#define NG 64
#define NOUT 16
#define NL 5
#define AROWS 104   // padded u32 (half2) row stride for fp16 activations

// ---------------- scratch (static __device__, no allocation) ----------------
static __device__ float g_x[N_NODESC * HID];                 // fp32 node features
static __device__ __align__(16) uint32_t g_h16[N_NODESC * AROWS]; // fp16x2 agg output
static __device__ __align__(16) uint32_t g_t16[N_NODESC * AROWS]; // fp16x2 GEMM1 output
static __device__ __align__(16) uint32_t g_wp[10 * 13 * HID * 8]; // packed weights [mid][t][n][kk]
static __device__ float g_etab[60 * HID];
static __device__ float g_alpha[NL * HID];
static __device__ float g_beta[NL * HID];
static __device__ int   g_deg[N_NODESC];
static __device__ int   g_off[N_NODESC + 1];
static __device__ int   g_cur[N_NODESC];
static __device__ int   g_packed[N_EDGESC];
static __device__ float g_pooled[(NL + 1) * NG * HID];
static __device__ int   g_counts[NG];

// ---------------- helpers ----------------
__device__ __forceinline__ uint32_t pack_f16x2(float even, float odd) {
    uint32_t r;
    asm("cvt.rn.f16x2.f32 %0, %1, %2;" : "=r"(r) : "f"(odd), "f"(even));
    return r;
}

__device__ __forceinline__ void mma_f16(float* c, uint32_t a0, uint32_t a1,
                                        uint32_t a2, uint32_t a3,
                                        uint32_t b0, uint32_t b1) {
    asm volatile(
        "mma.sync.aligned.m16n8k16.row.col.f32.f16.f16.f32 "
        "{%0,%1,%2,%3}, {%4,%5,%6,%7}, {%8,%9}, {%0,%1,%2,%3};\n"
        : "+f"(c[0]), "+f"(c[1]), "+f"(c[2]), "+f"(c[3])
        : "r"(a0), "r"(a1), "r"(a2), "r"(a3), "r"(b0), "r"(b1));
}

__device__ __forceinline__ void cp16(void* dst_smem, const void* src, bool full) {
    uint32_t d = (uint32_t)__cvta_generic_to_shared(dst_smem);
    int sz = full ? 16 : 0;
    asm volatile("cp.async.cg.shared.global [%0], [%1], 16, %2;\n"
                 :: "r"(d), "l"(src), "r"(sz) : "memory");
}

// ---------------- small setup kernels ----------------
__global__ void zero_scratch() {
    int i = blockIdx.x * blockDim.x + threadIdx.x;
    if (i < N_NODESC) { g_deg[i] = 0; g_cur[i] = 0; }
    if (i < NG) g_counts[i] = 0;
    int stride = gridDim.x * blockDim.x;
    for (int j = i; j < (NL + 1) * NG * HID; j += stride) g_pooled[j] = 0.f;
}

__global__ void node_emb_kernel(const int* __restrict__ kind, const int* __restrict__ content,
                                const float* __restrict__ kemb, const float* __restrict__ i2v,
                                const float* __restrict__ temb) {
    int n = blockIdx.x * 4 + (threadIdx.x >> 6);
    int t = threadIdx.x & 63;
    if (t >= HID4 || n >= N_NODESC) return;
    int k = kind[n];
    const float4* k4 = (const float4*)(kemb + k * HID);
    float4 v = k4[t];
    float4 w;
    if (k == 0) w = ((const float4*)(i2v + content[n] * HID))[t];
    else        w = ((const float4*)temb)[t];
    v.x += w.x; v.y += w.y; v.z += w.z; v.w += w.w;
    ((float4*)g_x)[n * HID4 + t] = v;
}

__global__ void etab_kernel(const float* __restrict__ etype_emb, const float* __restrict__ epos_emb) {
    int idx = blockIdx.x * blockDim.x + threadIdx.x;
    if (idx >= 60 * HID) return;
    int e = idx / HID, t = idx % HID;
    g_etab[idx] = etype_emb[(e / 20) * HID + t] + epos_emb[(e % 20) * HID + t];
}

__global__ void bnfold_kernel(const float* __restrict__ bn_g, const float* __restrict__ bn_b,
                              const float* __restrict__ bn_m, const float* __restrict__ bn_v,
                              const float* __restrict__ b1) {
    int idx = blockIdx.x * blockDim.x + threadIdx.x;
    if (idx >= NL * HID) return;
    float a = bn_g[idx] * rsqrtf(bn_v[idx] + 1e-5f);
    g_alpha[idx] = a;
    g_beta[idx] = (b1[idx] - bn_m[idx]) * a + bn_b[idx];
}

// pack weights: g_wp[mid][t][n][kk] = half2(W[16t+2kk][n], W[16t+2kk+1][n]); mid = l*2+m
__global__ void wpack_kernel(const float* __restrict__ W1, const float* __restrict__ W2) {
    int idx = blockIdx.x * blockDim.x + threadIdx.x;
    if (idx >= 10 * 13 * HID * 8) return;
    int mid = idx / (13 * HID * 8);
    int rem = idx % (13 * HID * 8);
    int t = rem / (HID * 8);
    int rem2 = rem % (HID * 8);
    int n = rem2 >> 3;
    int kk = rem2 & 7;
    int l = mid >> 1, m = mid & 1;
    const float* W = (m == 0) ? (W1 + l * HID * HID) : (W2 + l * HID * HID);
    int k0 = t * 16 + 2 * kk;
    float v0 = (k0 < HID) ? W[k0 * HID + n] : 0.f;
    float v1 = (k0 + 1 < HID) ? W[(k0 + 1) * HID + n] : 0.f;
    g_wp[idx] = pack_f16x2(v0, v1);
}

// ---------------- CSR build ----------------
__global__ void hist_kernel(const int* __restrict__ dst) {
    int j = blockIdx.x * blockDim.x + threadIdx.x;
    if (j < N_EDGESC) atomicAdd(&g_deg[dst[j]], 1);
}

__global__ void scan_kernel() {
    __shared__ int wsum[32];
    __shared__ int carry;
    int lt = threadIdx.x, lane = lt & 31, w = lt >> 5;
    if (lt == 0) { carry = 0; g_off[0] = 0; }
    __syncthreads();
    for (int base = 0; base < N_NODESC; base += 4096) {
        int i = base + lt * 4;
        int v0 = (i + 0 < N_NODESC) ? g_deg[i + 0] : 0;
        int v1 = (i + 1 < N_NODESC) ? g_deg[i + 1] : 0;
        int v2 = (i + 2 < N_NODESC) ? g_deg[i + 2] : 0;
        int v3 = (i + 3 < N_NODESC) ? g_deg[i + 3] : 0;
        int s0 = v0, s1 = s0 + v1, s2 = s1 + v2, s3 = s2 + v3;
        int tsc = s3;
#pragma unroll
        for (int o = 1; o < 32; o <<= 1) {
            int u = __shfl_up_sync(0xffffffffu, tsc, o);
            if (lane >= o) tsc += u;
        }
        if (lane == 31) wsum[w] = tsc;
        int texc = tsc - s3;
        __syncthreads();
        if (w == 0) {
            int ws = wsum[lane];
#pragma unroll
            for (int o = 1; o < 32; o <<= 1) {
                int u = __shfl_up_sync(0xffffffffu, ws, o);
                if (lane >= o) ws += u;
            }
            wsum[lane] = ws;
        }
        __syncthreads();
        int wexc = (w == 0) ? 0 : wsum[w - 1];
        int off = carry + wexc + texc;
        if (i + 0 < N_NODESC) g_off[i + 1] = off + s0;
        if (i + 1 < N_NODESC) g_off[i + 2] = off + s1;
        if (i + 2 < N_NODESC) g_off[i + 3] = off + s2;
        if (i + 3 < N_NODESC) g_off[i + 4] = off + s3;
        __syncthreads();
        if (lt == 0) carry = carry + wsum[31];
        __syncthreads();
    }
}

__global__ void scatter_kernel(const int* __restrict__ src, const int* __restrict__ dst,
                               const int* __restrict__ etype, const int* __restrict__ epos) {
    int j = blockIdx.x * blockDim.x + threadIdx.x;
    if (j >= N_EDGESC) return;
    int d = dst[j];
    int pos = g_off[d] + atomicAdd(&g_cur[d], 1);
    int ep = epos[j]; if (ep > 19) ep = 19;
    int ei = etype[j] * 20 + ep;
    g_packed[pos] = src[j] | (ei << 16);
}

__global__ void counts_kernel(const int* __restrict__ batch) {
    int i = blockIdx.x * blockDim.x + threadIdx.x;
    if (i < N_NODESC) atomicAdd(&g_counts[batch[i]], 1);
}

// ---------------- per-layer kernels ----------------
__device__ __forceinline__ float4 relu_add4(float4 a, float4 b) {
    float4 r;
    r.x = fmaxf(a.x + b.x, 0.f); r.y = fmaxf(a.y + b.y, 0.f);
    r.z = fmaxf(a.z + b.z, 0.f); r.w = fmaxf(a.w + b.w, 0.f);
    return r;
}
__device__ __forceinline__ void acc4(float4& a, float4 b) {
    a.x += b.x; a.y += b.y; a.z += b.z; a.w += b.w;
}

// h16[n] = fp16(x[n] + sum relu(x[src]+etab)); fp32 accumulation, write packed; 4 nodes/block
__global__ void __launch_bounds__(256) aggregate_kernel() {
    int n = blockIdx.x * 4 + (threadIdx.x >> 6);
    int t = threadIdx.x & 63;
    if (n >= N_NODESC) return;
    if (t >= 54) return;
    if (t >= HID4) {                       // zero-pad u32 cols [100,104)
        g_h16[(size_t)n * AROWS + 50 + t] = 0;
        return;
    }
    const float4* __restrict__ x4 = (const float4*)g_x;
    const float4* __restrict__ e4 = (const float4*)g_etab;
    float4 acc = x4[n * HID4 + t];
    int s0 = g_off[n], s1 = g_off[n + 1];
    int k = s0;
    for (; k + 3 < s1; k += 4) {
        int p0 = g_packed[k], p1 = g_packed[k + 1];
        int p2 = g_packed[k + 2], p3 = g_packed[k + 3];
        float4 a0 = x4[(p0 & 0xFFFF) * HID4 + t];
        float4 b0 = e4[(p0 >> 16) * HID4 + t];
        float4 a1 = x4[(p1 & 0xFFFF) * HID4 + t];
        float4 b1 = e4[(p1 >> 16) * HID4 + t];
        float4 a2 = x4[(p2 & 0xFFFF) * HID4 + t];
        float4 b2 = e4[(p2 >> 16) * HID4 + t];
        float4 a3 = x4[(p3 & 0xFFFF) * HID4 + t];
        float4 b3 = e4[(p3 >> 16) * HID4 + t];
        acc4(acc, relu_add4(a0, b0));
        acc4(acc, relu_add4(a1, b1));
        acc4(acc, relu_add4(a2, b2));
        acc4(acc, relu_add4(a3, b3));
    }
    for (; k < s1; k++) {
        int p = g_packed[k];
        acc4(acc, relu_add4(x4[(p & 0xFFFF) * HID4 + t], e4[(p >> 16) * HID4 + t]));
    }
    uint32_t* h = g_h16 + (size_t)n * AROWS;
    h[2 * t]     = pack_f16x2(acc.x, acc.y);
    h[2 * t + 1] = pack_f16x2(acc.z, acc.w);
}

// ---------------- FP16 tensor-core GEMM, cp.async 3-stage pipeline ----------------
// MODE 0: A=g_h16, out=g_t16 (fp16, BN-folded epilogue + relu)
// MODE 1: A=g_t16, out=g_x   (fp32, bias epilogue + relu)
template <int MODE>
__global__ void __launch_bounds__(256, 2) gemm_tc_kernel(const uint32_t* __restrict__ Wp,
                                                         const float* __restrict__ bias,
                                                         int layer) {
    const uint32_t* __restrict__ A = (MODE == 0) ? g_h16 : g_t16;

    __shared__ __align__(16) uint32_t As[3][128][12];
    __shared__ __align__(16) uint32_t Bs[3][104][12];

    const int tid = threadIdx.x;
    const int warp = tid >> 5, lane = tid & 31;
    const int grp = lane >> 2, qid = lane & 3;
    const int row0 = blockIdx.x * 128;
    const int col0 = blockIdx.y * 104;
    const int NT = (blockIdx.y == 0) ? 13 : 12;
    const int NC = NT * 8;
    const int ar = warp * 16 + grp;

    // copy roles: A: 128 rows x 8 u32 = 2 x 16B per row, 256 threads
    const int a_r = tid >> 1, a_half = tid & 1;
    const bool a_ok = (row0 + a_r) < N_NODESC;
    int a_row = a_ok ? (row0 + a_r) : (N_NODESC - 1);
    const uint32_t* a_src0 = A + (size_t)a_row * AROWS + a_half * 4;
    // B: NC cols x 8 u32 = 2 x 16B per col
    const int b_n = tid >> 1, b_half = tid & 1;
    const bool b_act = tid < 2 * NC;
    const uint32_t* b_src0 = Wp + (size_t)(col0 + (b_act ? b_n : 0)) * 8 + b_half * 4;

    float acc[13][4];
#pragma unroll
    for (int nt = 0; nt < 13; nt++)
#pragma unroll
        for (int j = 0; j < 4; j++) acc[nt][j] = 0.f;

#define ISSUE(T, S)                                                             \
    do {                                                                        \
        cp16(&As[S][a_r][a_half * 4], a_src0 + 8 * (T), a_ok);                  \
        if (b_act) cp16(&Bs[S][b_n][b_half * 4], b_src0 + (size_t)(T) * (HID * 8), true); \
        asm volatile("cp.async.commit_group;\n" ::: "memory");                  \
    } while (0)

    ISSUE(0, 0);
    ISSUE(1, 1);

    for (int t = 0; t < 13; t++) {
        const int s = t % 3;
        if (t < 12) asm volatile("cp.async.wait_group 1;\n" ::: "memory");
        else        asm volatile("cp.async.wait_group 0;\n" ::: "memory");
        __syncthreads();                       // tile-t data visible; prior MMA done
        if (t + 2 < 13) ISSUE(t + 2, (t + 2) % 3);

        uint32_t a0 = As[s][ar][qid];
        uint32_t a1 = As[s][ar + 8][qid];
        uint32_t a2 = As[s][ar][qid + 4];
        uint32_t a3 = As[s][ar + 8][qid + 4];
#pragma unroll
        for (int nt = 0; nt < 13; nt++) {
            if (nt < NT) {
                int n = nt * 8 + grp;
                uint32_t b0 = Bs[s][n][qid];
                uint32_t b1 = Bs[s][n][qid + 4];
                mma_f16(acc[nt], a0, a1, a2, a3, b0, b1);
            }
        }
    }
#undef ISSUE

    // ---- epilogue ----
    int r = row0 + warp * 16 + grp;
    bool ok0 = r < N_NODESC;
    bool ok1 = (r + 8) < N_NODESC;
    const float* abase = g_alpha + layer * HID;
    const float* bbase = g_beta + layer * HID;
#pragma unroll
    for (int nt = 0; nt < 13; nt++) {
        if (nt < NT) {
            int col = col0 + nt * 8 + 2 * qid;
            float v0 = acc[nt][0], v1 = acc[nt][1];
            float v2 = acc[nt][2], v3 = acc[nt][3];
            if (MODE == 0) {
                float a0 = abase[col], a1 = abase[col + 1];
                float bb0 = bbase[col], bb1 = bbase[col + 1];
                v0 = v0 * a0 + bb0; v1 = v1 * a1 + bb1;
                v2 = v2 * a0 + bb0; v3 = v3 * a1 + bb1;
            } else {
                float bi0 = bias[col], bi1 = bias[col + 1];
                v0 += bi0; v1 += bi1; v2 += bi0; v3 += bi1;
            }
            v0 = fmaxf(v0, 0.f); v1 = fmaxf(v1, 0.f);
            v2 = fmaxf(v2, 0.f); v3 = fmaxf(v3, 0.f);
            if (MODE == 0) {
                if (ok0) g_t16[(size_t)r * AROWS + (col >> 1)] = pack_f16x2(v0, v1);
                if (ok1) g_t16[(size_t)(r + 8) * AROWS + (col >> 1)] = pack_f16x2(v2, v3);
            } else {
                if (ok0) *(float2*)(g_x + (size_t)r * HID + col) = make_float2(v0, v1);
                if (ok1) *(float2*)(g_x + (size_t)(r + 8) * HID + col) = make_float2(v2, v3);
            }
        }
    }
    // zero-pad g_t16 tail cols (only needed once; y==0 CTAs do it)
    if (MODE == 0 && blockIdx.y == 0 && tid < 128 && (row0 + tid) < N_NODESC) {
        uint4 z = make_uint4(0, 0, 0, 0);
        *(uint4*)&g_t16[(size_t)(row0 + tid) * AROWS + 100] = z;
    }
}

// run-accumulated segment-sum pooling over sorted batch_vec (float4 lanes)
__global__ void __launch_bounds__(64) pool_kernel(const int* __restrict__ batch, int layer) {
    int t = threadIdx.x;
    if (t >= HID4) return;
    int i0 = blockIdx.x * 64;
    int i1 = i0 + 64; if (i1 > N_NODESC) i1 = N_NODESC;
    if (i0 >= N_NODESC) return;
    const float4* __restrict__ x4 = (const float4*)g_x;
    float* pooled = g_pooled + layer * NG * HID;
    float4 acc = make_float4(0.f, 0.f, 0.f, 0.f);
    int cur = batch[i0];
    for (int i = i0; i < i1; i++) {
        int g = batch[i];
        if (g != cur) {
            float* p = pooled + cur * HID + t * 4;
            atomicAdd(p + 0, acc.x); atomicAdd(p + 1, acc.y);
            atomicAdd(p + 2, acc.z); atomicAdd(p + 3, acc.w);
            acc = make_float4(0.f, 0.f, 0.f, 0.f);
            cur = g;
        }
        acc4(acc, x4[i * HID4 + t]);
    }
    float* p = pooled + cur * HID + t * 4;
    atomicAdd(p + 0, acc.x); atomicAdd(p + 1, acc.y);
    atomicAdd(p + 2, acc.z); atomicAdd(p + 3, acc.w);
}

__global__ void final_kernel(const float* __restrict__ fcW, const float* __restrict__ fcb,
                             float* __restrict__ out) {
    __shared__ float red[256];
    int g = blockIdx.x;
    int t = threadIdx.x;
    int o = t & 15, seg = t >> 4;
    float acc = 0.f;
    for (int i = 0; i < NL + 1; i++) {
        const float* p = g_pooled + (i * NG + g) * HID;
        const float* w = fcW + i * HID * NOUT;
        for (int tt = seg; tt < HID; tt += 16)
            acc += p[tt] * w[tt * NOUT + o];
    }
    red[t] = acc;
    __syncthreads();
    for (int s = 8; s >= 1; s >>= 1) {
        if (seg < s) red[t] += red[t + s * 16];
        __syncthreads();
    }
    if (seg == 0) {
        float bias = 0.f;
        for (int i = 0; i < NL + 1; i++) bias += fcb[i * NOUT + o];
        float cnt = fmaxf((float)g_counts[g], 1.f);
        out[g * NOUT + o] = red[o] / cnt + bias;
    }
}

// ---------------- launch ----------------
extern "C" void kernel_launch(void* const* d_in, const int* in_sizes, int n_in,
                              void* d_out, int out_size) {
    (void)in_sizes; (void)n_in; (void)out_size;
    const int* node_kind    = (const int*)d_in[0];
    const int* node_content = (const int*)d_in[1];
    const int* edge_index   = (const int*)d_in[2];
    const int* edge_type    = (const int*)d_in[3];
    const int* edge_pos     = (const int*)d_in[4];
    const int* batch_vec    = (const int*)d_in[5];
    const float* kind_emb   = (const float*)d_in[6];
    const float* inst2vec   = (const float*)d_in[7];
    const float* type_emb   = (const float*)d_in[8];
    const float* etype_emb  = (const float*)d_in[9];
    const float* epos_emb   = (const float*)d_in[10];
    const float* W1         = (const float*)d_in[11];
    const float* b1         = (const float*)d_in[12];
    const float* bn_g       = (const float*)d_in[13];
    const float* bn_b       = (const float*)d_in[14];
    const float* bn_m       = (const float*)d_in[15];
    const float* bn_v       = (const float*)d_in[16];
    const float* W2         = (const float*)d_in[17];
    const float* b2         = (const float*)d_in[18];
    const float* fc_W       = (const float*)d_in[19];
    const float* fc_b       = (const float*)d_in[20];
    float* out = (float*)d_out;

    const int* src = edge_index;
    const int* dst = edge_index + N_EDGESC;

    zero_scratch<<<(N_NODESC + 255) / 256, 256>>>();
    node_emb_kernel<<<(N_NODESC + 3) / 4, 256>>>(node_kind, node_content, kind_emb, inst2vec, type_emb);
    etab_kernel<<<(60 * HID + 255) / 256, 256>>>(etype_emb, epos_emb);
    bnfold_kernel<<<(NL * HID + 255) / 256, 256>>>(bn_g, bn_b, bn_m, bn_v, b1);
    wpack_kernel<<<(10 * 13 * HID * 8 + 255) / 256, 256>>>(W1, W2);

    hist_kernel<<<(N_EDGESC + 255) / 256, 256>>>(dst);
    scan_kernel<<<1, 1024>>>();
    scatter_kernel<<<(N_EDGESC + 255) / 256, 256>>>(src, dst, edge_type, edge_pos);
    counts_kernel<<<(N_NODESC + 255) / 256, 256>>>(batch_vec);

    uint32_t* wp = nullptr;
    cudaGetSymbolAddress((void**)&wp, g_wp);   // host-side query, graph-safe (no alloc)

    dim3 ggrid((N_NODESC + 127) / 128, 2);
    pool_kernel<<<(N_NODESC + 63) / 64, 64>>>(batch_vec, 0);
    for (int l = 0; l < NL; l++) {
        aggregate_kernel<<<(N_NODESC + 3) / 4, 256>>>();
        gemm_tc_kernel<0><<<ggrid, 256>>>(wp + (size_t)(l * 2 + 0) * 13 * HID * 8, nullptr, l);
        gemm_tc_kernel<1><<<ggrid, 256>>>(wp + (size_t)(l * 2 + 1) * 13 * HID * 8, b2 + l * HID, l);
        pool_kernel<<<(N_NODESC + 63) / 64, 64>>>(batch_vec, l + 1);
    }
    final_kernel<<<NG, 256>>>(fc_W, fc_b, out);
}